// round 16
// baseline (speedup 1.0000x reference)
#include <cuda_runtime.h>
#include <cuda_bf16.h>

typedef unsigned long long u64;
typedef unsigned int u32;

#define Bn   2
#define Sn   1024
#define Hn   768
#define Dn   24
#define HIDn 96

// ---------------- scratch ----------------
__device__ float g_Zj  [Bn*Sn*Dn];
__device__ float g_Zi  [Bn*Sn*Dn];
__device__ float g_Cj  [Bn*Sn*HIDn];   // Ws1[:,0:24]@Zj + b1
__device__ float g_P   [Bn*Sn*Sn];
__device__ float g_ctxA[Bn*Sn*Hn];
__device__ float g_ctxB[Bn*Sn*Hn];
__device__ float g_h1A [Bn*Sn*Hn];
__device__ float g_h1B [Bn*Sn*Hn];

// ---------------- helpers ----------------
__device__ __forceinline__ u32 f2tf32(float f){
    u32 r;
    asm("cvt.rna.tf32.f32 %0, %1;" : "=r"(r) : "f"(f));
    return r;
}
__device__ __forceinline__ void mma_tf32(
    float& d0, float& d1, float& d2, float& d3,
    u32 a0, u32 a1, u32 a2, u32 a3, u32 b0, u32 b1)
{
    asm("mma.sync.aligned.m16n8k8.row.col.f32.tf32.tf32.f32 "
        "{%0,%1,%2,%3},{%4,%5,%6,%7},{%8,%9},{%0,%1,%2,%3};"
        : "+f"(d0), "+f"(d1), "+f"(d2), "+f"(d3)
        : "r"(a0), "r"(a1), "r"(a2), "r"(a3), "r"(b0), "r"(b1));
}

// =================== kernel 1: projections + per-j MLP term ===================
__global__ __launch_bounds__(256) void k_proj(
    const float* __restrict__ Hj, const float* __restrict__ Hi,
    const float* __restrict__ Wpj, const float* __restrict__ Wpi,
    const float* __restrict__ Ws1, const float* __restrict__ bs1)
{
    __shared__ float shj[Hn], shi[Hn];
    __shared__ float sz[48];
    __shared__ float sws1[96][25];
    const int row = blockIdx.x;
    const int t = threadIdx.x;
    const float* hj = Hj + (size_t)row*Hn;
    const float* hi = Hi + (size_t)row*Hn;
    for (int k = t; k < Hn; k += 256){ shj[k] = hj[k]; shi[k] = hi[k]; }
    for (int idx = t; idx < 96*24; idx += 256) sws1[idx/24][idx%24] = Ws1[(idx/24)*96 + (idx%24)];
    __syncthreads();

    const int w = t >> 5, lane = t & 31;
    for (int o = w; o < 48; o += 8){
        const float* wv = (o < 24) ? (Wpj + (size_t)o*Hn) : (Wpi + (size_t)(o-24)*Hn);
        const float* x  = (o < 24) ? shj : shi;
        float s0 = 0.f, s1 = 0.f;
        #pragma unroll
        for (int h = lane; h < Hn; h += 64){
            s0 = fmaf(wv[h],    x[h],    s0);
            s1 = fmaf(wv[h+32], x[h+32], s1);
        }
        float s = s0 + s1;
        #pragma unroll
        for (int off = 16; off; off >>= 1) s += __shfl_xor_sync(0xffffffffu, s, off);
        if (lane == 0){
            sz[o] = s;
            if (o < 24) g_Zj[(size_t)row*24 + o]      = s;
            else        g_Zi[(size_t)row*24 + (o-24)] = s;
        }
    }
    __syncthreads();

    if (t < 96){
        float s = bs1[t];
        #pragma unroll
        for (int d = 0; d < 24; d++) s = fmaf(sws1[t][d], sz[d], s);
        g_Cj[(size_t)row*96 + t] = s;
    }
}

// =================== kernel 2: pair MLP via tf32 mma, K=72, double-buffered build ===================
#define JT 64
#define IT 128

#define OFF_ASW  0                            // 1728 uint4 = 27648
#define OFF_BDYN 27648                        // 2 x 3072 uint2 = 49152
#define OFF_BZI  (27648+49152)                // 1536 uint2 = 12288
#define OFF_ZI   (OFF_BZI+12288)              // 128*25 f = 12800
#define OFF_ZJ   (OFF_ZI+12800)               // 64*25 f = 6400
#define OFF_CJ   (OFF_ZJ+6400)                // 2*96 f = 768
#define OFF_WS2  (OFF_CJ+768)                 // 96 f = 384
#define SMEM_PAIR (OFF_WS2+384)               // 109,440 B

__global__ __launch_bounds__(256, 2) void k_pair_mma(
    const float* __restrict__ Ws1, const float* __restrict__ Ws2,
    const float* __restrict__ bs2)
{
    extern __shared__ __align__(16) char smem[];
    uint4* Asw  = (uint4*)(smem + OFF_ASW);
    uint2* Bdyn = (uint2*)(smem + OFF_BDYN);
    uint2* Bzi  = (uint2*)(smem + OFF_BZI);
    float* Zi_s = (float*)(smem + OFF_ZI);
    float* Zj_s = (float*)(smem + OFF_ZJ);
    float* Cj_s = (float*)(smem + OFF_CJ);
    float* ws2s = (float*)(smem + OFF_WS2);

    const int t  = threadIdx.x;
    const int i0 = blockIdx.x * IT;
    const int j0 = blockIdx.y * JT;
    const int b  = blockIdx.z;
    const int base = b * Sn;
    const int w = t >> 5, lane = t & 31;
    const int g = lane >> 2, t4 = lane & 3;

    for (int idx = t; idx < 1728; idx += 256){
        int mt = idx / 288, r = idx % 288, kt = r / 32, ln = r % 32;
        int gg = ln >> 2, tt = ln & 3;
        int h = mt*16 + gg;
        int k0 = kt*8 + tt, k1 = k0 + 4;
        int c0 = (k0 < 48) ? 48 + k0 : k0 - 24;
        int c1 = (k1 < 48) ? 48 + k1 : k1 - 24;
        uint4 v;
        v.x = f2tf32(Ws1[h*96 + c0]);
        v.y = f2tf32(Ws1[(h+8)*96 + c0]);
        v.z = f2tf32(Ws1[h*96 + c1]);
        v.w = f2tf32(Ws1[(h+8)*96 + c1]);
        Asw[idx] = v;
    }
    for (int idx = t; idx < IT*24; idx += 256){
        int r = idx / 24, k = idx % 24;
        Zi_s[r*25 + k] = g_Zi[(size_t)(base + i0 + r)*24 + k];
    }
    for (int idx = t; idx < JT*24; idx += 256){
        int r = idx / 24, k = idx % 24;
        Zj_s[r*25 + k] = g_Zj[(size_t)(base + j0 + r)*24 + k];
    }
    if (t < 96) ws2s[t] = Ws2[t];
    const float bs2v = bs2[0];
    __syncthreads();

    // static Zi B fragments (kt 6..8)
    for (int e = t; e < 1536; e += 256){
        int ktl = e >> 9, ww = (e >> 6) & 7, nt = (e >> 5) & 1, ln = e & 31;
        int gg = ln >> 2, tt = ln & 3;
        int col = ww*16 + nt*8 + gg;
        int k0 = ktl*8 + tt, k1 = k0 + 4;
        uint2 u;
        u.x = f2tf32(Zi_s[col*25 + k0]);
        u.y = f2tf32(Zi_s[col*25 + k1]);
        Bzi[e] = u;
    }

    // feature builder for row jn into buffer p
    auto build = [&](int jn, int p){
        if (t < 96) Cj_s[p*96 + t] = g_Cj[(size_t)(base + j0 + jn)*96 + t];
        const float* zj = &Zj_s[jn*25];
        uint2* dst = Bdyn + p*3072;
        #pragma unroll
        for (int q = 0; q < 12; q++){
            int e = t + q*256;
            int kt = e >> 9, ww = (e >> 6) & 7, nt = (e >> 5) & 1, ln = e & 31;
            int gg = ln >> 2, tt = ln & 3;
            int col = ww*16 + nt*8 + gg;
            int k0 = kt*8 + tt, k1 = k0 + 4;
            const float* zi = &Zi_s[col*25];
            float f0, f1;
            if (kt < 3){ f0 = zj[k0]*zi[k0]; f1 = zj[k1]*zi[k1]; }
            else { f0 = fabsf(zj[k0-24] - zi[k0-24]); f1 = fabsf(zj[k1-24] - zi[k1-24]); }
            uint2 u; u.x = f2tf32(f0); u.y = f2tf32(f1);
            dst[e] = u;
        }
    };

    build(0, 0);
    __syncthreads();

    for (int jj = 0; jj < JT; jj++){
        const int p = jj & 1;

        // pull this j's fragments/coeffs into registers (reads buffer p)
        u32 bf[2][9][2];
        #pragma unroll
        for (int nt = 0; nt < 2; nt++){
            #pragma unroll
            for (int kt = 0; kt < 6; kt++){
                uint2 u = Bdyn[p*3072 + ((kt*8 + w)*2 + nt)*32 + lane];
                bf[nt][kt][0] = u.x; bf[nt][kt][1] = u.y;
            }
            #pragma unroll
            for (int kt = 6; kt < 9; kt++){
                uint2 u = Bzi[(((kt-6)*8 + w)*2 + nt)*32 + lane];
                bf[nt][kt][0] = u.x; bf[nt][kt][1] = u.y;
            }
        }
        float cjv[6][2];
        #pragma unroll
        for (int mt = 0; mt < 6; mt++){
            cjv[mt][0] = Cj_s[p*96 + mt*16 + g];
            cjv[mt][1] = Cj_s[p*96 + mt*16 + g + 8];
        }

        // overlap: build next j into the other buffer
        if (jj + 1 < JT) build(jj + 1, p ^ 1);

        float pA[4] = {0.f, 0.f, 0.f, 0.f};
        #pragma unroll
        for (int mt = 0; mt < 6; mt++){
            uint4 af[9];
            #pragma unroll
            for (int kt = 0; kt < 9; kt++) af[kt] = Asw[(mt*9 + kt)*32 + lane];
            const float wsa = ws2s[mt*16 + g],  wsb = ws2s[mt*16 + g + 8];
            #pragma unroll
            for (int nt = 0; nt < 2; nt++){
                float d0 = 0.f, d1 = 0.f, d2 = 0.f, d3 = 0.f;
                #pragma unroll
                for (int kt = 0; kt < 9; kt++)
                    mma_tf32(d0, d1, d2, d3,
                             af[kt].x, af[kt].y, af[kt].z, af[kt].w,
                             bf[nt][kt][0], bf[nt][kt][1]);
                float v0 = fmaxf(d0 + cjv[mt][0], 0.f);
                float v1 = fmaxf(d1 + cjv[mt][0], 0.f);
                float v2 = fmaxf(d2 + cjv[mt][1], 0.f);
                float v3 = fmaxf(d3 + cjv[mt][1], 0.f);
                pA[nt*2]   = fmaf(wsa, v0, fmaf(wsb, v2, pA[nt*2]));
                pA[nt*2+1] = fmaf(wsa, v1, fmaf(wsb, v3, pA[nt*2+1]));
            }
        }
        #pragma unroll
        for (int q = 0; q < 4; q++){
            pA[q] += __shfl_xor_sync(0xffffffffu, pA[q], 4);
            pA[q] += __shfl_xor_sync(0xffffffffu, pA[q], 8);
            pA[q] += __shfl_xor_sync(0xffffffffu, pA[q], 16);
        }
        if (g == 0){
            float* dst = &g_P[(size_t)(base + j0 + jj)*Sn + i0 + w*16];
            *(float2*)(dst + 2*t4)     = make_float2(pA[0] + bs2v, pA[1] + bs2v);
            *(float2*)(dst + 8 + 2*t4) = make_float2(pA[2] + bs2v, pA[3] + bs2v);
        }
        __syncthreads();
    }
}

// =================== kernel 3: masked softmax over i (in place) ===================
__global__ __launch_bounds__(256) void k_softmax(const float* __restrict__ mask){
    const int r = blockIdx.x;
    const int b = r / Sn;
    float* row = g_P + (size_t)r*Sn;
    const float* mrow = mask + (size_t)b*Sn;
    const int t = threadIdx.x;
    __shared__ float red[256];

    float vals[4]; float mx = -3.402823466e38f;
    #pragma unroll
    for (int q = 0; q < 4; q++){
        int i = t + q*256;
        float v = row[i] + (1.0f - mrow[i]) * (-3.402823466e38f);
        vals[q] = v; mx = fmaxf(mx, v);
    }
    red[t] = mx; __syncthreads();
    for (int s = 128; s > 0; s >>= 1){ if (t < s) red[t] = fmaxf(red[t], red[t+s]); __syncthreads(); }
    mx = red[0]; __syncthreads();

    float sum = 0.f;
    #pragma unroll
    for (int q = 0; q < 4; q++){ vals[q] = __expf(vals[q] - mx); sum += vals[q]; }
    red[t] = sum; __syncthreads();
    for (int s = 128; s > 0; s >>= 1){ if (t < s) red[t] += red[t+s]; __syncthreads(); }
    float inv = 1.0f / red[0];
    #pragma unroll
    for (int q = 0; q < 4; q++) row[t + q*256] = vals[q] * inv;
}

// =================== tf32 tensor-core GEMM, balanced frag staging (R14) ===================
template<int MODE>
__global__ __launch_bounds__(256) void k_gemm_t(
    const float* __restrict__ BW,
    const float* __restrict__ Hj,
    const float* __restrict__ bias,    // MODE2: bv1
    const float* __restrict__ bias2,   // MODE2: bv2
    const float* __restrict__ alpha_p,
    float* __restrict__ Cout)
{
    constexpr int KH = (MODE == 0) ? 512 : (MODE == 1) ? 1152 : 768;
    constexpr int T  = KH / 16;
    constexpr int KW = (MODE == 1) ? 2304 : 768;

    __shared__ __align__(16) uint4 Af[2][2][4][32];
    __shared__ __align__(16) uint2 Bf[2][2][8][2][32];
    u32* Afu = (u32*)Af;
    u32* Bfu = (u32*)Bf;

    const int t  = threadIdx.x;
    const int n0 = blockIdx.x * 128;
    const int m0 = blockIdx.y * 64;
    int b = 0, ks = 0;
    if (MODE == 0){ b = blockIdx.z >> 1; ks = blockIdx.z & 1; }
    if (MODE == 1){ ks = blockIdx.z; }
    const int rowbase = (MODE == 0) ? b*Sn + m0 : m0;
    const int kbase   = ks * KH;

    const int w = t >> 5, lane = t & 31;
    const int g = lane >> 2, t4 = lane & 3;

    const bool isB = (t < 128);
    const int bn  = t;
    const int bww = bn >> 4, bnt = (bn >> 3) & 1, bgg = bn & 7;
    const int a   = t - 128;
    const int ah8 = a & 1;
    const int akt = (a >> 1) & 1;
    const int agg = (a >> 2) & 7;
    const int amt = (a >> 5) & 3;
    const int mrow = amt*16 + agg;

    const float* Bsrc = (MODE == 0) ? (BW + (size_t)b*Sn*Hn) : BW;

    float br[16];
    float2 a00, a01, a10, a11;

    auto loadA2 = [&](int m, int ko) -> float2 {
        if (MODE == 0){
            return *(const float2*)(g_P + (size_t)(rowbase + m)*Sn + kbase + ko);
        } else if (MODE == 2){
            const float2 xa = *(const float2*)(g_h1A + (size_t)(rowbase + m)*Hn + ko);
            const float2 xb = *(const float2*)(g_h1B + (size_t)(rowbase + m)*Hn + ko);
            const float2 bb = *(const float2*)(bias + ko);
            return make_float2(fmaxf(xa.x+xb.x+bb.x,0.f), fmaxf(xa.y+xb.y+bb.y,0.f));
        } else {
            const int fo = kbase + ko;
            const float* rCA = g_ctxA + (size_t)(rowbase + m)*Hn;
            const float* rCB = g_ctxB + (size_t)(rowbase + m)*Hn;
            const float* rH  = Hj + (size_t)(rowbase + m)*Hn;
            if (fo < 768){
                float2 c = *(const float2*)(rCA + fo);
                float2 d = *(const float2*)(rCB + fo);
                return make_float2(c.x+d.x, c.y+d.y);
            } else if (fo < 1536){
                return *(const float2*)(rH + fo - 768);
            } else {
                const int go = fo - 1536;
                float2 c = *(const float2*)(rCA + go);
                float2 d = *(const float2*)(rCB + go);
                float2 h = *(const float2*)(rH + go);
                return make_float2((c.x+d.x)*h.x, (c.y+d.y)*h.y);
            }
        }
    };

    auto ldg = [&](int ck){
        const int kb = ck * 16;
        if (isB){
            if (MODE == 0){
                #pragma unroll
                for (int c = 0; c < 16; c++)
                    br[c] = Bsrc[(size_t)(kbase + kb + c)*Hn + n0 + bn];
            } else {
                const float* s = Bsrc + (size_t)(n0 + bn)*KW + kbase + kb;
                float4 q0 = *(const float4*)s;
                float4 q1 = *(const float4*)(s + 4);
                float4 q2 = *(const float4*)(s + 8);
                float4 q3 = *(const float4*)(s + 12);
                br[0]=q0.x; br[1]=q0.y; br[2]=q0.z; br[3]=q0.w;
                br[4]=q1.x; br[5]=q1.y; br[6]=q1.z; br[7]=q1.w;
                br[8]=q2.x; br[9]=q2.y; br[10]=q2.z; br[11]=q2.w;
                br[12]=q3.x; br[13]=q3.y; br[14]=q3.z; br[15]=q3.w;
            }
        } else {
            const int ko = kb + akt*8;
            a00 = loadA2(mrow,     ko + 2*ah8);
            a01 = loadA2(mrow,     ko + 4 + 2*ah8);
            a10 = loadA2(mrow + 8, ko + 2*ah8);
            a11 = loadA2(mrow + 8, ko + 4 + 2*ah8);
        }
    };

    auto sts = [&](int buf){
        if (isB){
            #pragma unroll
            for (int kt = 0; kt < 2; kt++){
                u32 tmp[8];
                #pragma unroll
                for (int h = 0; h < 2; h++)
                    #pragma unroll
                    for (int tt = 0; tt < 4; tt++)
                        tmp[tt*2 + h] = f2tf32(br[kt*8 + h*4 + tt]);
                const u32 base = ((((buf*2 + kt)*8 + bww)*2 + bnt)*32)*2 + bgg*8;
                *(uint4*)&Bfu[base]     = make_uint4(tmp[0], tmp[1], tmp[2], tmp[3]);
                *(uint4*)&Bfu[base + 4] = make_uint4(tmp[4], tmp[5], tmp[6], tmp[7]);
            }
        } else {
            u32 tmp[8];
            tmp[0] = f2tf32(a00.x);
            tmp[1] = f2tf32(a10.x);
            tmp[2] = f2tf32(a01.x);
            tmp[3] = f2tf32(a11.x);
            tmp[4] = f2tf32(a00.y);
            tmp[5] = f2tf32(a10.y);
            tmp[6] = f2tf32(a01.y);
            tmp[7] = f2tf32(a11.y);
            const u32 base = (((buf*2 + akt)*4 + amt)*32)*4 + agg*16 + ah8*8;
            *(uint4*)&Afu[base]     = make_uint4(tmp[0], tmp[1], tmp[2], tmp[3]);
            *(uint4*)&Afu[base + 4] = make_uint4(tmp[4], tmp[5], tmp[6], tmp[7]);
        }
    };

    float acc[4][2][4];
    #pragma unroll
    for (int mt = 0; mt < 4; mt++)
        #pragma unroll
        for (int nt = 0; nt < 2; nt++)
            #pragma unroll
            for (int q = 0; q < 4; q++) acc[mt][nt][q] = 0.f;

    ldg(0); sts(0); __syncthreads();

    for (int tt = 0; tt < T; tt++){
        const int cur = tt & 1;
        if (tt + 1 < T) ldg(tt + 1);
        #pragma unroll
        for (int kt = 0; kt < 2; kt++){
            uint2 bfr[2];
            bfr[0] = Bf[cur][kt][w][0][lane];
            bfr[1] = Bf[cur][kt][w][1][lane];
            uint4 afr[4];
            #pragma unroll
            for (int mt = 0; mt < 4; mt++) afr[mt] = Af[cur][kt][mt][lane];
            #pragma unroll
            for (int mt = 0; mt < 4; mt++)
                #pragma unroll
                for (int nt = 0; nt < 2; nt++)
                    mma_tf32(acc[mt][nt][0], acc[mt][nt][1], acc[mt][nt][2], acc[mt][nt][3],
                             afr[mt].x, afr[mt].y, afr[mt].z, afr[mt].w,
                             bfr[nt].x, bfr[nt].y);
        }
        if (tt + 1 < T) sts(cur ^ 1);
        __syncthreads();
    }

    const float alpha = (MODE == 2) ? alpha_p[0] : 1.0f;
    const int wbase = n0 + w*16;
    float2 badd[2];
    if (MODE == 2){
        badd[0] = *(const float2*)(bias2 + wbase + 2*t4);
        badd[1] = *(const float2*)(bias2 + wbase + 8 + 2*t4);
    }
    #pragma unroll
    for (int mt = 0; mt < 4; mt++){
        #pragma unroll
        for (int nt = 0; nt < 2; nt++){
            const int col = wbase + nt*8 + 2*t4;
            float2 v0 = make_float2(acc[mt][nt][0], acc[mt][nt][1]);
            float2 v1 = make_float2(acc[mt][nt][2], acc[mt][nt][3]);
            if (MODE == 2){
                v0.x = (v0.x + badd[nt].x) * alpha; v0.y = (v0.y + badd[nt].y) * alpha;
                v1.x = (v1.x + badd[nt].x) * alpha; v1.y = (v1.y + badd[nt].y) * alpha;
            }
            float* dstbuf;
            if      (MODE == 0) dstbuf = (ks == 0 ? g_ctxA : g_ctxB);
            else if (MODE == 1) dstbuf = (ks == 0 ? g_h1A  : g_h1B );
            else                dstbuf = Cout;
            *(float2*)(dstbuf + (size_t)(rowbase + mt*16 + g)*Hn + col)     = v0;
            *(float2*)(dstbuf + (size_t)(rowbase + mt*16 + g + 8)*Hn + col) = v1;
        }
    }
}

// =============================== launch ===============================
extern "C" void kernel_launch(void* const* d_in, const int* in_sizes, int n_in,
                              void* d_out, int out_size)
{
    const float* Hj    = (const float*)d_in[0];
    const float* Hi    = (const float*)d_in[1];
    const float* mask  = (const float*)d_in[2];
    const float* Wpj   = (const float*)d_in[3];
    const float* Wpi   = (const float*)d_in[4];
    const float* Ws1   = (const float*)d_in[5];
    const float* bs1   = (const float*)d_in[6];
    const float* Ws2   = (const float*)d_in[7];
    const float* bs2   = (const float*)d_in[8];
    const float* Wv1   = (const float*)d_in[9];
    const float* bv1   = (const float*)d_in[10];
    const float* Wv2   = (const float*)d_in[11];
    const float* bv2   = (const float*)d_in[12];
    const float* alpha = (const float*)d_in[13];
    float* out = (float*)d_out;

    cudaFuncSetAttribute(k_pair_mma, cudaFuncAttributeMaxDynamicSharedMemorySize, SMEM_PAIR);

    k_proj<<<Bn*Sn, 256>>>(Hj, Hi, Wpj, Wpi, Ws1, bs1);

    dim3 gp(Sn/IT, Sn/JT, Bn);
    k_pair_mma<<<gp, 256, SMEM_PAIR>>>(Ws1, Ws2, bs2);

    k_softmax<<<Bn*Sn, 256>>>(mask);

    dim3 g0(Hn/128, Sn/64, Bn*2);
    k_gemm_t<0><<<g0, 256>>>(Hi, nullptr, nullptr, nullptr, nullptr, nullptr);

    dim3 g1(Hn/128, (Bn*Sn)/64, 2);
    k_gemm_t<1><<<g1, 256>>>(Wv1, Hj, nullptr, nullptr, nullptr, nullptr);

    dim3 g2(Hn/128, (Bn*Sn)/64, 1);
    k_gemm_t<2><<<g2, 256>>>(Wv2, nullptr, bv1, bv2, alpha, out);
}

// round 17
// speedup vs baseline: 1.0221x; 1.0221x over previous
#include <cuda_runtime.h>
#include <cuda_bf16.h>

typedef unsigned long long u64;
typedef unsigned int u32;

#define Bn   2
#define Sn   1024
#define Hn   768
#define Dn   24
#define HIDn 96
#define FK   2304

// ---------------- scratch ----------------
__device__ float g_Zj  [Bn*Sn*Dn];
__device__ float g_Zi  [Bn*Sn*Dn];
__device__ float g_Cj  [Bn*Sn*HIDn];   // Ws1[:,0:24]@Zj + b1
__device__ float g_P   [Bn*Sn*Sn];
__device__ float g_ctxA[Bn*Sn*Hn];
__device__ float g_ctxB[Bn*Sn*Hn];
__device__ float g_h1A [Bn*Sn*Hn];
__device__ float g_h1B [Bn*Sn*Hn];
__device__ float g_h1R [Bn*Sn*Hn];
__device__ float g_feat[Bn*Sn*FK];

// ---------------- helpers ----------------
__device__ __forceinline__ u32 f2tf32(float f){
    u32 r;
    asm("cvt.rna.tf32.f32 %0, %1;" : "=r"(r) : "f"(f));
    return r;
}
__device__ __forceinline__ void mma_tf32(
    float& d0, float& d1, float& d2, float& d3,
    u32 a0, u32 a1, u32 a2, u32 a3, u32 b0, u32 b1)
{
    asm("mma.sync.aligned.m16n8k8.row.col.f32.tf32.tf32.f32 "
        "{%0,%1,%2,%3},{%4,%5,%6,%7},{%8,%9},{%0,%1,%2,%3};"
        : "+f"(d0), "+f"(d1), "+f"(d2), "+f"(d3)
        : "r"(a0), "r"(a1), "r"(a2), "r"(a3), "r"(b0), "r"(b1));
}

// =================== kernel 1: projections + per-j MLP term ===================
__global__ __launch_bounds__(256) void k_proj(
    const float* __restrict__ Hj, const float* __restrict__ Hi,
    const float* __restrict__ Wpj, const float* __restrict__ Wpi,
    const float* __restrict__ Ws1, const float* __restrict__ bs1)
{
    __shared__ float shj[Hn], shi[Hn];
    __shared__ float sz[48];
    __shared__ float sws1[96][25];
    const int row = blockIdx.x;
    const int t = threadIdx.x;
    const float* hj = Hj + (size_t)row*Hn;
    const float* hi = Hi + (size_t)row*Hn;
    for (int k = t; k < Hn; k += 256){ shj[k] = hj[k]; shi[k] = hi[k]; }
    for (int idx = t; idx < 96*24; idx += 256) sws1[idx/24][idx%24] = Ws1[(idx/24)*96 + (idx%24)];
    __syncthreads();

    const int w = t >> 5, lane = t & 31;
    for (int o = w; o < 48; o += 8){
        const float* wv = (o < 24) ? (Wpj + (size_t)o*Hn) : (Wpi + (size_t)(o-24)*Hn);
        const float* x  = (o < 24) ? shj : shi;
        float s0 = 0.f, s1 = 0.f;
        #pragma unroll
        for (int h = lane; h < Hn; h += 64){
            s0 = fmaf(wv[h],    x[h],    s0);
            s1 = fmaf(wv[h+32], x[h+32], s1);
        }
        float s = s0 + s1;
        #pragma unroll
        for (int off = 16; off; off >>= 1) s += __shfl_xor_sync(0xffffffffu, s, off);
        if (lane == 0){
            sz[o] = s;
            if (o < 24) g_Zj[(size_t)row*24 + o]      = s;
            else        g_Zi[(size_t)row*24 + (o-24)] = s;
        }
    }
    __syncthreads();

    if (t < 96){
        float s = bs1[t];
        #pragma unroll
        for (int d = 0; d < 24; d++) s = fmaf(sws1[t][d], sz[d], s);
        g_Cj[(size_t)row*96 + t] = s;
    }
}

// =================== kernel 2: pair MLP via tf32 mma, K=72 (R15, unchanged) ===================
#define JT 64
#define IT 128

#define OFF_ASW  0
#define OFF_BDYN 27648
#define OFF_BZI  (27648+49152)
#define OFF_ZI   (OFF_BZI+12288)
#define OFF_ZJ   (OFF_ZI+12800)
#define OFF_CJ   (OFF_ZJ+6400)
#define OFF_WS2  (OFF_CJ+768)
#define SMEM_PAIR (OFF_WS2+384)

__global__ __launch_bounds__(256, 2) void k_pair_mma(
    const float* __restrict__ Ws1, const float* __restrict__ Ws2,
    const float* __restrict__ bs2)
{
    extern __shared__ __align__(16) char smem[];
    uint4* Asw  = (uint4*)(smem + OFF_ASW);
    uint2* Bdyn = (uint2*)(smem + OFF_BDYN);
    uint2* Bzi  = (uint2*)(smem + OFF_BZI);
    float* Zi_s = (float*)(smem + OFF_ZI);
    float* Zj_s = (float*)(smem + OFF_ZJ);
    float* Cj_s = (float*)(smem + OFF_CJ);
    float* ws2s = (float*)(smem + OFF_WS2);

    const int t  = threadIdx.x;
    const int i0 = blockIdx.x * IT;
    const int j0 = blockIdx.y * JT;
    const int b  = blockIdx.z;
    const int base = b * Sn;
    const int w = t >> 5, lane = t & 31;
    const int g = lane >> 2, t4 = lane & 3;

    for (int idx = t; idx < 1728; idx += 256){
        int mt = idx / 288, r = idx % 288, kt = r / 32, ln = r % 32;
        int gg = ln >> 2, tt = ln & 3;
        int h = mt*16 + gg;
        int k0 = kt*8 + tt, k1 = k0 + 4;
        int c0 = (k0 < 48) ? 48 + k0 : k0 - 24;
        int c1 = (k1 < 48) ? 48 + k1 : k1 - 24;
        uint4 v;
        v.x = f2tf32(Ws1[h*96 + c0]);
        v.y = f2tf32(Ws1[(h+8)*96 + c0]);
        v.z = f2tf32(Ws1[h*96 + c1]);
        v.w = f2tf32(Ws1[(h+8)*96 + c1]);
        Asw[idx] = v;
    }
    for (int idx = t; idx < IT*24; idx += 256){
        int r = idx / 24, k = idx % 24;
        Zi_s[r*25 + k] = g_Zi[(size_t)(base + i0 + r)*24 + k];
    }
    for (int idx = t; idx < JT*24; idx += 256){
        int r = idx / 24, k = idx % 24;
        Zj_s[r*25 + k] = g_Zj[(size_t)(base + j0 + r)*24 + k];
    }
    if (t < 96) ws2s[t] = Ws2[t];
    const float bs2v = bs2[0];
    __syncthreads();

    for (int e = t; e < 1536; e += 256){
        int ktl = e >> 9, ww = (e >> 6) & 7, nt = (e >> 5) & 1, ln = e & 31;
        int gg = ln >> 2, tt = ln & 3;
        int col = ww*16 + nt*8 + gg;
        int k0 = ktl*8 + tt, k1 = k0 + 4;
        uint2 u;
        u.x = f2tf32(Zi_s[col*25 + k0]);
        u.y = f2tf32(Zi_s[col*25 + k1]);
        Bzi[e] = u;
    }

    auto build = [&](int jn, int p){
        if (t < 96) Cj_s[p*96 + t] = g_Cj[(size_t)(base + j0 + jn)*96 + t];
        const float* zj = &Zj_s[jn*25];
        uint2* dst = Bdyn + p*3072;
        #pragma unroll
        for (int q = 0; q < 12; q++){
            int e = t + q*256;
            int kt = e >> 9, ww = (e >> 6) & 7, nt = (e >> 5) & 1, ln = e & 31;
            int gg = ln >> 2, tt = ln & 3;
            int col = ww*16 + nt*8 + gg;
            int k0 = kt*8 + tt, k1 = k0 + 4;
            const float* zi = &Zi_s[col*25];
            float f0, f1;
            if (kt < 3){ f0 = zj[k0]*zi[k0]; f1 = zj[k1]*zi[k1]; }
            else { f0 = fabsf(zj[k0-24] - zi[k0-24]); f1 = fabsf(zj[k1-24] - zi[k1-24]); }
            uint2 u; u.x = f2tf32(f0); u.y = f2tf32(f1);
            dst[e] = u;
        }
    };

    build(0, 0);
    __syncthreads();

    for (int jj = 0; jj < JT; jj++){
        const int p = jj & 1;

        u32 bf[2][9][2];
        #pragma unroll
        for (int nt = 0; nt < 2; nt++){
            #pragma unroll
            for (int kt = 0; kt < 6; kt++){
                uint2 u = Bdyn[p*3072 + ((kt*8 + w)*2 + nt)*32 + lane];
                bf[nt][kt][0] = u.x; bf[nt][kt][1] = u.y;
            }
            #pragma unroll
            for (int kt = 6; kt < 9; kt++){
                uint2 u = Bzi[(((kt-6)*8 + w)*2 + nt)*32 + lane];
                bf[nt][kt][0] = u.x; bf[nt][kt][1] = u.y;
            }
        }
        float cjv[6][2];
        #pragma unroll
        for (int mt = 0; mt < 6; mt++){
            cjv[mt][0] = Cj_s[p*96 + mt*16 + g];
            cjv[mt][1] = Cj_s[p*96 + mt*16 + g + 8];
        }

        if (jj + 1 < JT) build(jj + 1, p ^ 1);

        float pA[4] = {0.f, 0.f, 0.f, 0.f};
        #pragma unroll
        for (int mt = 0; mt < 6; mt++){
            uint4 af[9];
            #pragma unroll
            for (int kt = 0; kt < 9; kt++) af[kt] = Asw[(mt*9 + kt)*32 + lane];
            const float wsa = ws2s[mt*16 + g],  wsb = ws2s[mt*16 + g + 8];
            #pragma unroll
            for (int nt = 0; nt < 2; nt++){
                float d0 = 0.f, d1 = 0.f, d2 = 0.f, d3 = 0.f;
                #pragma unroll
                for (int kt = 0; kt < 9; kt++)
                    mma_tf32(d0, d1, d2, d3,
                             af[kt].x, af[kt].y, af[kt].z, af[kt].w,
                             bf[nt][kt][0], bf[nt][kt][1]);
                float v0 = fmaxf(d0 + cjv[mt][0], 0.f);
                float v1 = fmaxf(d1 + cjv[mt][0], 0.f);
                float v2 = fmaxf(d2 + cjv[mt][1], 0.f);
                float v3 = fmaxf(d3 + cjv[mt][1], 0.f);
                pA[nt*2]   = fmaf(wsa, v0, fmaf(wsb, v2, pA[nt*2]));
                pA[nt*2+1] = fmaf(wsa, v1, fmaf(wsb, v3, pA[nt*2+1]));
            }
        }
        #pragma unroll
        for (int q = 0; q < 4; q++){
            pA[q] += __shfl_xor_sync(0xffffffffu, pA[q], 4);
            pA[q] += __shfl_xor_sync(0xffffffffu, pA[q], 8);
            pA[q] += __shfl_xor_sync(0xffffffffu, pA[q], 16);
        }
        if (g == 0){
            float* dst = &g_P[(size_t)(base + j0 + jj)*Sn + i0 + w*16];
            *(float2*)(dst + 2*t4)     = make_float2(pA[0] + bs2v, pA[1] + bs2v);
            *(float2*)(dst + 8 + 2*t4) = make_float2(pA[2] + bs2v, pA[3] + bs2v);
        }
        __syncthreads();
    }
}

// =================== kernel 3: masked softmax over i (in place) ===================
__global__ __launch_bounds__(256) void k_softmax(const float* __restrict__ mask){
    const int r = blockIdx.x;
    const int b = r / Sn;
    float* row = g_P + (size_t)r*Sn;
    const float* mrow = mask + (size_t)b*Sn;
    const int t = threadIdx.x;
    __shared__ float red[256];

    float vals[4]; float mx = -3.402823466e38f;
    #pragma unroll
    for (int q = 0; q < 4; q++){
        int i = t + q*256;
        float v = row[i] + (1.0f - mrow[i]) * (-3.402823466e38f);
        vals[q] = v; mx = fmaxf(mx, v);
    }
    red[t] = mx; __syncthreads();
    for (int s = 128; s > 0; s >>= 1){ if (t < s) red[t] = fmaxf(red[t], red[t+s]); __syncthreads(); }
    mx = red[0]; __syncthreads();

    float sum = 0.f;
    #pragma unroll
    for (int q = 0; q < 4; q++){ vals[q] = __expf(vals[q] - mx); sum += vals[q]; }
    red[t] = sum; __syncthreads();
    for (int s = 128; s > 0; s >>= 1){ if (t < s) red[t] += red[t+s]; __syncthreads(); }
    float inv = 1.0f / red[0];
    #pragma unroll
    for (int q = 0; q < 4; q++) row[t + q*256] = vals[q] * inv;
}

// =================== kernel 3b: materialize feat = [ctx | Hj | ctx*Hj] ===================
__global__ __launch_bounds__(256) void k_feat(const float* __restrict__ Hj){
    const int row = blockIdx.x;                    // 0..Bn*Sn-1
    const int t = threadIdx.x;
    const float* ca = g_ctxA + (size_t)row*Hn;
    const float* cb = g_ctxB + (size_t)row*Hn;
    const float* hj = Hj + (size_t)row*Hn;
    float* f = g_feat + (size_t)row*FK;
    for (int i = t; i < Hn/4; i += 256){
        float4 a = *(const float4*)(ca + i*4);
        float4 b = *(const float4*)(cb + i*4);
        float4 h = *(const float4*)(hj + i*4);
        float4 c = make_float4(a.x+b.x, a.y+b.y, a.z+b.z, a.w+b.w);
        *(float4*)(f + i*4)            = c;
        *(float4*)(f + Hn + i*4)       = h;
        *(float4*)(f + 2*Hn + i*4)     = make_float4(c.x*h.x, c.y*h.y, c.z*h.z, c.w*h.w);
    }
}

// =================== kernel 3c: h1R = relu(h1A + h1B + bv1) ===================
__global__ __launch_bounds__(256) void k_relu(const float* __restrict__ bv1){
    const int row = blockIdx.x;
    const int t = threadIdx.x;
    const float* a = g_h1A + (size_t)row*Hn;
    const float* b = g_h1B + (size_t)row*Hn;
    float* o = g_h1R + (size_t)row*Hn;
    for (int i = t; i < Hn/4; i += 256){
        float4 xa = *(const float4*)(a + i*4);
        float4 xb = *(const float4*)(b + i*4);
        float4 bb = *(const float4*)(bv1 + i*4);
        *(float4*)(o + i*4) = make_float4(
            fmaxf(xa.x+xb.x+bb.x, 0.f), fmaxf(xa.y+xb.y+bb.y, 0.f),
            fmaxf(xa.z+xb.z+bb.z, 0.f), fmaxf(xa.w+xb.w+bb.w, 0.f));
    }
}

// =================== tf32 tensor-core GEMM, uniform contiguous A ===================
// MODE 0: ctx partial = P[:, ks] @ Hi[ks, :]        (K=512 per half, A=g_P)
// MODE 1: h1 partial  = feat[:, ks] @ Wv1[:, ks]^T  (K=1152 per half, A=g_feat)
// MODE 2: out = alpha*( h1R @ Wv2^T + bv2 )         (K=768, A=g_h1R)
template<int MODE>
__global__ __launch_bounds__(256) void k_gemm_t(
    const float* __restrict__ BW,
    const float* __restrict__ bias2,   // MODE2: bv2
    const float* __restrict__ alpha_p,
    float* __restrict__ Cout)
{
    constexpr int KH = (MODE == 0) ? 512 : (MODE == 1) ? 1152 : 768;
    constexpr int T  = KH / 16;
    constexpr int KW = (MODE == 1) ? 2304 : 768;
    constexpr int AS = (MODE == 0) ? Sn : (MODE == 1) ? FK : Hn;   // A row stride

    __shared__ __align__(16) uint4 Af[2][2][4][32];
    __shared__ __align__(16) uint2 Bf[2][2][8][2][32];
    u32* Afu = (u32*)Af;
    u32* Bfu = (u32*)Bf;

    const int t  = threadIdx.x;
    const int n0 = blockIdx.x * 128;
    const int m0 = blockIdx.y * 64;
    int b = 0, ks = 0;
    if (MODE == 0){ b = blockIdx.z >> 1; ks = blockIdx.z & 1; }
    if (MODE == 1){ ks = blockIdx.z; }
    const int rowbase = (MODE == 0) ? b*Sn + m0 : m0;
    const int kbase   = ks * KH;

    const int w = t >> 5, lane = t & 31;
    const int g = lane >> 2, t4 = lane & 3;

    const bool isB = (t < 128);
    const int bn  = t;
    const int bww = bn >> 4, bnt = (bn >> 3) & 1, bgg = bn & 7;
    const int a   = t - 128;
    const int ah8 = a & 1;
    const int akt = (a >> 1) & 1;
    const int agg = (a >> 2) & 7;
    const int amt = (a >> 5) & 3;
    const int mrow = amt*16 + agg;

    const float* Bsrc = (MODE == 0) ? (BW + (size_t)b*Sn*Hn) : BW;
    const float* Asrc = (MODE == 0) ? g_P : (MODE == 1) ? g_feat : g_h1R;
    const float* Arow0 = Asrc + (size_t)(rowbase + mrow)*AS + kbase;
    const float* Arow1 = Asrc + (size_t)(rowbase + mrow + 8)*AS + kbase;

    float br[16];
    float2 a00, a01, a10, a11;

    auto ldg = [&](int ck){
        const int kb = ck * 16;
        if (isB){
            if (MODE == 0){
                #pragma unroll
                for (int c = 0; c < 16; c++)
                    br[c] = Bsrc[(size_t)(kbase + kb + c)*Hn + n0 + bn];
            } else {
                const float* s = Bsrc + (size_t)(n0 + bn)*KW + kbase + kb;
                float4 q0 = *(const float4*)s;
                float4 q1 = *(const float4*)(s + 4);
                float4 q2 = *(const float4*)(s + 8);
                float4 q3 = *(const float4*)(s + 12);
                br[0]=q0.x; br[1]=q0.y; br[2]=q0.z; br[3]=q0.w;
                br[4]=q1.x; br[5]=q1.y; br[6]=q1.z; br[7]=q1.w;
                br[8]=q2.x; br[9]=q2.y; br[10]=q2.z; br[11]=q2.w;
                br[12]=q3.x; br[13]=q3.y; br[14]=q3.z; br[15]=q3.w;
            }
        } else {
            const int ko = kb + akt*8 + 2*ah8;
            a00 = *(const float2*)(Arow0 + ko);
            a01 = *(const float2*)(Arow0 + ko + 4);
            a10 = *(const float2*)(Arow1 + ko);
            a11 = *(const float2*)(Arow1 + ko + 4);
        }
    };

    auto sts = [&](int buf){
        if (isB){
            #pragma unroll
            for (int kt = 0; kt < 2; kt++){
                u32 tmp[8];
                #pragma unroll
                for (int h = 0; h < 2; h++)
                    #pragma unroll
                    for (int tt = 0; tt < 4; tt++)
                        tmp[tt*2 + h] = f2tf32(br[kt*8 + h*4 + tt]);
                const u32 base = ((((buf*2 + kt)*8 + bww)*2 + bnt)*32)*2 + bgg*8;
                *(uint4*)&Bfu[base]     = make_uint4(tmp[0], tmp[1], tmp[2], tmp[3]);
                *(uint4*)&Bfu[base + 4] = make_uint4(tmp[4], tmp[5], tmp[6], tmp[7]);
            }
        } else {
            u32 tmp[8];
            tmp[0] = f2tf32(a00.x);
            tmp[1] = f2tf32(a10.x);
            tmp[2] = f2tf32(a01.x);
            tmp[3] = f2tf32(a11.x);
            tmp[4] = f2tf32(a00.y);
            tmp[5] = f2tf32(a10.y);
            tmp[6] = f2tf32(a01.y);
            tmp[7] = f2tf32(a11.y);
            const u32 base = (((buf*2 + akt)*4 + amt)*32)*4 + agg*16 + ah8*8;
            *(uint4*)&Afu[base]     = make_uint4(tmp[0], tmp[1], tmp[2], tmp[3]);
            *(uint4*)&Afu[base + 4] = make_uint4(tmp[4], tmp[5], tmp[6], tmp[7]);
        }
    };

    float acc[4][2][4];
    #pragma unroll
    for (int mt = 0; mt < 4; mt++)
        #pragma unroll
        for (int nt = 0; nt < 2; nt++)
            #pragma unroll
            for (int q = 0; q < 4; q++) acc[mt][nt][q] = 0.f;

    ldg(0); sts(0); __syncthreads();

    for (int tt = 0; tt < T; tt++){
        const int cur = tt & 1;
        if (tt + 1 < T) ldg(tt + 1);
        #pragma unroll
        for (int kt = 0; kt < 2; kt++){
            uint2 bfr[2];
            bfr[0] = Bf[cur][kt][w][0][lane];
            bfr[1] = Bf[cur][kt][w][1][lane];
            uint4 afr[4];
            #pragma unroll
            for (int mt = 0; mt < 4; mt++) afr[mt] = Af[cur][kt][mt][lane];
            #pragma unroll
            for (int mt = 0; mt < 4; mt++)
                #pragma unroll
                for (int nt = 0; nt < 2; nt++)
                    mma_tf32(acc[mt][nt][0], acc[mt][nt][1], acc[mt][nt][2], acc[mt][nt][3],
                             afr[mt].x, afr[mt].y, afr[mt].z, afr[mt].w,
                             bfr[nt].x, bfr[nt].y);
        }
        if (tt + 1 < T) sts(cur ^ 1);
        __syncthreads();
    }

    const float alpha = (MODE == 2) ? alpha_p[0] : 1.0f;
    const int wbase = n0 + w*16;
    float2 badd[2];
    if (MODE == 2){
        badd[0] = *(const float2*)(bias2 + wbase + 2*t4);
        badd[1] = *(const float2*)(bias2 + wbase + 8 + 2*t4);
    }
    #pragma unroll
    for (int mt = 0; mt < 4; mt++){
        #pragma unroll
        for (int nt = 0; nt < 2; nt++){
            const int col = wbase + nt*8 + 2*t4;
            float2 v0 = make_float2(acc[mt][nt][0], acc[mt][nt][1]);
            float2 v1 = make_float2(acc[mt][nt][2], acc[mt][nt][3]);
            if (MODE == 2){
                v0.x = (v0.x + badd[nt].x) * alpha; v0.y = (v0.y + badd[nt].y) * alpha;
                v1.x = (v1.x + badd[nt].x) * alpha; v1.y = (v1.y + badd[nt].y) * alpha;
            }
            float* dstbuf;
            if      (MODE == 0) dstbuf = (ks == 0 ? g_ctxA : g_ctxB);
            else if (MODE == 1) dstbuf = (ks == 0 ? g_h1A  : g_h1B );
            else                dstbuf = Cout;
            *(float2*)(dstbuf + (size_t)(rowbase + mt*16 + g)*Hn + col)     = v0;
            *(float2*)(dstbuf + (size_t)(rowbase + mt*16 + g + 8)*Hn + col) = v1;
        }
    }
}

// =============================== launch ===============================
extern "C" void kernel_launch(void* const* d_in, const int* in_sizes, int n_in,
                              void* d_out, int out_size)
{
    const float* Hj    = (const float*)d_in[0];
    const float* Hi    = (const float*)d_in[1];
    const float* mask  = (const float*)d_in[2];
    const float* Wpj   = (const float*)d_in[3];
    const float* Wpi   = (const float*)d_in[4];
    const float* Ws1   = (const float*)d_in[5];
    const float* bs1   = (const float*)d_in[6];
    const float* Ws2   = (const float*)d_in[7];
    const float* bs2   = (const float*)d_in[8];
    const float* Wv1   = (const float*)d_in[9];
    const float* bv1   = (const float*)d_in[10];
    const float* Wv2   = (const float*)d_in[11];
    const float* bv2   = (const float*)d_in[12];
    const float* alpha = (const float*)d_in[13];
    float* out = (float*)d_out;

    cudaFuncSetAttribute(k_pair_mma, cudaFuncAttributeMaxDynamicSharedMemorySize, SMEM_PAIR);

    k_proj<<<Bn*Sn, 256>>>(Hj, Hi, Wpj, Wpi, Ws1, bs1);

    dim3 gp(Sn/IT, Sn/JT, Bn);
    k_pair_mma<<<gp, 256, SMEM_PAIR>>>(Ws1, Ws2, bs2);

    k_softmax<<<Bn*Sn, 256>>>(mask);

    dim3 g0(Hn/128, Sn/64, Bn*2);
    k_gemm_t<0><<<g0, 256>>>(Hi, nullptr, nullptr, nullptr);

    k_feat<<<Bn*Sn, 256>>>(Hj);

    dim3 g1(Hn/128, (Bn*Sn)/64, 2);
    k_gemm_t<1><<<g1, 256>>>(Wv1, nullptr, nullptr, nullptr);

    k_relu<<<Bn*Sn, 256>>>(bv1);

    dim3 g2(Hn/128, (Bn*Sn)/64, 1);
    k_gemm_t<2><<<g2, 256>>>(Wv2, bv2, alpha, out);
}